// round 10
// baseline (speedup 1.0000x reference)
#include <cuda_runtime.h>
#include <cuda_bf16.h>

#define Bn 2
#define Cc 32
#define Hh 32
#define Nn 128
#define Ff 32
#define Ee 16256          // N*(N-1)
#define NM1 127
#define LN_EPS 1e-5f

// ---------------- scratch (device globals; no allocation) ----------------
__device__ float g_A  [Bn*Hh*Nn*Ff];   // fc1(conv(sender-part))
__device__ float g_Bc [Bn*Hh*Nn*Ff];   // fc1(conv(receiver-part)) + bias terms
__device__ float g_X  [Bn*Hh*Ee*Ff];   // pre-LN edge activations (133 MB)
__device__ float g_part[Bn*Hh*Nn*2];   // per-(b,h,r) partial (sum, sumsq)
__device__ float g_stats[Bn*Hh*2];     // (mu, invstd) per (b,h)
__device__ float g_att [Bn*Ee*Ff];     // attention (4.2 MB)
__device__ float g_inc [Bn*Hh*Nn*Ff];  // incoming (already /N)
__device__ float g_incm[Bn*Hh*Nn*Ff];  // incoming after node MLP

__device__ __forceinline__ float silu_f(float x) {
    return x * __frcp_rn(1.f + __expf(-x));
}
__device__ __forceinline__ float sigm_f(float x) {
    return __frcp_rn(1.f + __expf(-x));
}

// ---------------- K1: per-node A / Bc precompute ----------------
__global__ void k1_node_pre(const float* __restrict__ node,
                            const float* __restrict__ ecw,
                            const float* __restrict__ ecb,
                            const float* __restrict__ f1w,
                            const float* __restrict__ f1b) {
    int bid = blockIdx.x;                 // (b,h,n) linear
    int n = bid & (Nn-1);
    int h = (bid >> 7) & (Hh-1);
    int b = bid >> 12;
    int g = threadIdx.x;

    const float* np_ = node + ((b*Cc)*Nn + n)*Ff + g;
    const float* w   = ecw + h*2*Cc;
    float S = 0.f, R = 0.f;
#pragma unroll
    for (int c = 0; c < Cc; c++) {
        float v = np_[c*Nn*Ff];
        S += w[c]      * v;
        R += w[Cc + c] * v;
    }
    float A0=0.f,A1=0.f,A2=0.f,A3=0.f, B0=0.f,B1=0.f,B2=0.f,B3=0.f, rs=0.f;
#pragma unroll
    for (int f = 0; f < Ff; f += 4) {
        float w0 = f1w[g*Ff + f+0], w1 = f1w[g*Ff + f+1];
        float w2_ = f1w[g*Ff + f+2], w3 = f1w[g*Ff + f+3];
        A0 += w0 * __shfl_sync(0xffffffffu, S, f+0);
        A1 += w1 * __shfl_sync(0xffffffffu, S, f+1);
        A2 += w2_ * __shfl_sync(0xffffffffu, S, f+2);
        A3 += w3 * __shfl_sync(0xffffffffu, S, f+3);
        B0 += w0 * __shfl_sync(0xffffffffu, R, f+0);
        B1 += w1 * __shfl_sync(0xffffffffu, R, f+1);
        B2 += w2_ * __shfl_sync(0xffffffffu, R, f+2);
        B3 += w3 * __shfl_sync(0xffffffffu, R, f+3);
        rs += w0 + w1 + w2_ + w3;
    }
    int o = ((b*Hh + h)*Nn + n)*Ff + g;
    g_A [o] = (A0+A1)+(A2+A3);
    g_Bc[o] = (B0+B1)+(B2+B3) + ecb[h]*rs + f1b[g];
}

// ---------------- K2: edge pass A (phase-split, FFMA2) ----------------
// block = (b,h,r), 256 threads.
// Phase A: u-tile (32 q x 127 e) into smem transposed, ONE barrier.
// Phase B: fc2 matvec, 4 edges per warp-iter, broadcast LDS.128 + fma.rn.f32x2.
__global__ void k2_edgeA(const float* __restrict__ f2w,
                         const float* __restrict__ f2b) {
    int bid = blockIdx.x;                 // (b,h,r)
    int r = bid & (Nn-1);
    int h = (bid >> 7) & (Hh-1);
    int b = bid >> 12;
    int f = threadIdx.x & 31;             // lane: phase A = q (fc1 dim), phase B = output f
    int w = threadIdx.x >> 5;             // warp 0..7
    int bh = b*Hh + h;

    __shared__ __align__(16) float uT[32*132];   // row=q (stride 132), col=e
    __shared__ float sm[16];

    // ---- phase A: u = silu(A[s] + Bc[r]) ----
    float bc = g_Bc[(bh*Nn + r)*Ff + f];
    const float* Abase = g_A + (size_t)bh*Nn*Ff + f;
    for (int e = w; e < NM1; e += 8) {
        int s = e + (e >= r);
        uT[f*132 + e] = silu_f(Abase[s*Ff] + bc);
    }
    if (threadIdx.x < 32) uT[threadIdx.x*132 + 127] = 0.f;   // pad edge

    // w2 row for this output f, packed (w,w) for f32x2
    unsigned long long ww[32];
#pragma unroll
    for (int k = 0; k < 32; k++) {
        float wv = f2w[f*Ff + k];
        asm("mov.b64 %0, {%1, %1};" : "=l"(ww[k]) : "f"(wv));
    }
    float b2 = f2b[f];
    __syncthreads();

    // ---- phase B: x = silu(fc2(u)), stream 4 edges per iter, no syncs ----
    float s1 = 0.f, s2 = 0.f;
    int ebase = bh*Ee + r*NM1;
    const float4* uT4 = (const float4*)uT;       // row stride 33 float4
#pragma unroll
    for (int i = 0; i < 4; i++) {
        int g4 = w*4 + i;                 // group 0..31, edges e0..e0+3
        int e0 = g4*4;
        unsigned long long acc01, acc23;
        asm("mov.b64 %0, {%1, %1};" : "=l"(acc01) : "f"(b2));
        acc23 = acc01;
#pragma unroll
        for (int k = 0; k < 32; k++) {
            float4 u4 = uT4[k*33 + g4];   // broadcast, 16B aligned
            unsigned long long u01, u23;
            asm("mov.b64 %0, {%1, %2};" : "=l"(u01) : "f"(u4.x), "f"(u4.y));
            asm("mov.b64 %0, {%1, %2};" : "=l"(u23) : "f"(u4.z), "f"(u4.w));
            asm("fma.rn.f32x2 %0, %1, %2, %0;" : "+l"(acc01) : "l"(ww[k]), "l"(u01));
            asm("fma.rn.f32x2 %0, %1, %2, %0;" : "+l"(acc23) : "l"(ww[k]), "l"(u23));
        }
        float v0, v1, v2, v3;
        asm("mov.b64 {%0, %1}, %2;" : "=f"(v0), "=f"(v1) : "l"(acc01));
        asm("mov.b64 {%0, %1}, %2;" : "=f"(v2), "=f"(v3) : "l"(acc23));
        float x0 = silu_f(v0), x1 = silu_f(v1), x2 = silu_f(v2), x3 = silu_f(v3);
        // coalesced stores (lane = f contiguous), skip pad edge 127
        g_X[(size_t)(ebase + e0 + 0)*Ff + f] = x0; s1 += x0; s2 += x0*x0;
        g_X[(size_t)(ebase + e0 + 1)*Ff + f] = x1; s1 += x1; s2 += x1*x1;
        g_X[(size_t)(ebase + e0 + 2)*Ff + f] = x2; s1 += x2; s2 += x2*x2;
        if (e0 + 3 < NM1) {
            g_X[(size_t)(ebase + e0 + 3)*Ff + f] = x3; s1 += x3; s2 += x3*x3;
        }
    }

    // ---- stats reduce ----
#pragma unroll
    for (int o = 16; o; o >>= 1) {
        s1 += __shfl_down_sync(0xffffffffu, s1, o);
        s2 += __shfl_down_sync(0xffffffffu, s2, o);
    }
    if (f == 0) { sm[w] = s1; sm[8 + w] = s2; }
    __syncthreads();
    if (threadIdx.x == 0) {
        float t1 = 0.f, t2 = 0.f;
#pragma unroll
        for (int q = 0; q < 8; q++) { t1 += sm[q]; t2 += sm[8+q]; }
        g_part[(bh*Nn + r)*2 + 0] = t1;
        g_part[(bh*Nn + r)*2 + 1] = t2;
    }
}

// ---------------- K3: finalize LN stats per (b,h) ----------------
__global__ void k3_stats() {
    int bh = blockIdx.x;
    int t  = threadIdx.x;                 // 0..127 = r
    float s1 = g_part[(bh*Nn + t)*2 + 0];
    float s2 = g_part[(bh*Nn + t)*2 + 1];
#pragma unroll
    for (int o = 16; o; o >>= 1) {
        s1 += __shfl_down_sync(0xffffffffu, s1, o);
        s2 += __shfl_down_sync(0xffffffffu, s2, o);
    }
    __shared__ float sm[8];
    if ((t & 31) == 0) { sm[t >> 5] = s1; sm[4 + (t >> 5)] = s2; }
    __syncthreads();
    if (t == 0) {
        float T1 = sm[0] + sm[1] + sm[2] + sm[3];
        float T2 = sm[4] + sm[5] + sm[6] + sm[7];
        const float invc = 1.f / (float)(Ee * Ff);
        float mu  = T1 * invc;
        float var = T2 * invc - mu*mu;
        g_stats[bh*2 + 0] = mu;
        g_stats[bh*2 + 1] = rsqrtf(var + LN_EPS);
    }
}

// ---------------- K4a: attention (h-reduction factored out) ----------------
__global__ void k4a_att(const float* __restrict__ emask,
                        const float* __restrict__ lng,
                        const float* __restrict__ lnb,
                        const float* __restrict__ attw,
                        const float* __restrict__ attb) {
    int b  = blockIdx.y;
    int i4 = blockIdx.x * blockDim.x + threadIdx.x;   // float4 index into (E,F)

    __shared__ float swh[Hh];
    __shared__ float sc[2];                            // c1, c0
    if (threadIdx.x < Hh) {
        int h = threadIdx.x;
        swh[h] = attw[h] * g_stats[(b*Hh + h)*2 + 1];
    }
    __syncthreads();
    if (threadIdx.x == 0) {
        float c1 = 0.f, c0 = 0.f;
#pragma unroll
        for (int h = 0; h < Hh; h++) {
            c1 += swh[h] * g_stats[(b*Hh + h)*2 + 0];
            c0 += attw[h];
        }
        sc[0] = c1; sc[1] = c0;
    }
    __syncthreads();

    const float4* xb = (const float4*)(g_X + (size_t)b*Hh*Ee*Ff) + i4;
    float4 T = make_float4(0.f, 0.f, 0.f, 0.f);
#pragma unroll
    for (int h = 0; h < Hh; h++) {
        float wv = swh[h];
        float4 x = xb[(size_t)h * (Ee*Ff/4)];
        T.x += wv*x.x; T.y += wv*x.y; T.z += wv*x.z; T.w += wv*x.w;
    }
    float c1 = sc[0], c0 = sc[1];
    float ab = attb[0];
    int e = i4 >> 3;                                  // 8 float4 per edge row
    float em = emask[b*Ee + e];
    float4 lg = ((const float4*)lng)[i4];
    float4 lb = ((const float4*)lnb)[i4];
    float4 a;
    a.x = sigm_f(em*(lg.x*(T.x - c1) + lb.x*c0) + ab);
    a.y = sigm_f(em*(lg.y*(T.y - c1) + lb.y*c0) + ab);
    a.z = sigm_f(em*(lg.z*(T.z - c1) + lb.z*c0) + ab);
    a.w = sigm_f(em*(lg.w*(T.w - c1) + lb.w*c0) + ab);
    ((float4*)(g_att + (size_t)b*Ee*Ff))[i4] = a;
}

// ---------------- K4b: mij out + segmented incoming — float4, no loop barriers ----------------
__global__ void k4b_edgeB(const float* __restrict__ emask,
                          const float* __restrict__ lng,
                          const float* __restrict__ lnb,
                          float* __restrict__ out_mij) {
    int bid = blockIdx.x;
    int r = bid & (Nn-1);
    int h = (bid >> 7) & (Hh-1);
    int b = bid >> 12;
    int tid = threadIdx.x;
    int f4  = tid & 7;                    // which float4 of the 32-f row
    int bh = b*Hh + h;

    float mu  = g_stats[bh*2 + 0];
    float inv = g_stats[bh*2 + 1];

    const float4* xb  = (const float4*)(g_X    + (size_t)bh*Ee*Ff);
    float4*       mo  = (float4*)      (out_mij + (size_t)bh*Ee*Ff);
    const float4* atp = (const float4*)(g_att  + (size_t)b*Ee*Ff);
    const float4* lgp = (const float4*)lng;
    const float4* lbp = (const float4*)lnb;
    const float*  emb = emask + b*Ee;

    int e0 = r*NM1;
    int jr = tid >> 3;                    // 0..15
    float4 acc = make_float4(0.f, 0.f, 0.f, 0.f);
#pragma unroll 2
    for (int j = jr; j < NM1; j += 16) {
        int e = e0 + j;
        int o = e*8 + f4;
        float  em = emb[e];
        float4 x  = xb[o];
        float4 lg = lgp[o];
        float4 lb = lbp[o];
        float4 at = atp[o];
        float4 m1, mv;
        m1.x = ((x.x - mu)*inv*lg.x + lb.x) * em;
        m1.y = ((x.y - mu)*inv*lg.y + lb.y) * em;
        m1.z = ((x.z - mu)*inv*lg.z + lb.z) * em;
        m1.w = ((x.w - mu)*inv*lg.w + lb.w) * em;
        mv.x = m1.x * em; mv.y = m1.y * em; mv.z = m1.z * em; mv.w = m1.w * em;
        mo[o] = mv;
        acc.x += m1.x * at.x * em;
        acc.y += m1.y * at.y * em;
        acc.z += m1.z * at.z * em;
        acc.w += m1.w * at.w * em;
    }

    __shared__ float sacc[128*4];
    *(float4*)&sacc[tid*4] = acc;
    __syncthreads();
    if (tid < 32) {
        int c = tid >> 2, comp = tid & 3; // f = c*4 + comp == tid
        float t = 0.f;
#pragma unroll
        for (int k = 0; k < 16; k++) t += sacc[(c + 8*k)*4 + comp];
        g_inc[(bh*Nn + r)*Ff + tid] = t * (1.f/(float)Nn);
    }
}

// ---------------- node-side MLP4d: one block per (b,h'), whole LN in-block ----------------
template<int MODE>
__global__ void k_node_mlp(const float* __restrict__ node,
                           const float* __restrict__ cw,
                           const float* __restrict__ cb,
                           const float* __restrict__ f1w,
                           const float* __restrict__ f1b,
                           const float* __restrict__ f2w,
                           const float* __restrict__ f2b,
                           const float* __restrict__ lg,
                           const float* __restrict__ lb,
                           const float* __restrict__ nmask,
                           float* __restrict__ out) {
    int hp = blockIdx.x & (Hh-1);
    int b  = blockIdx.x >> 5;
    int f  = threadIdx.x & 31;
    int w  = threadIdx.x >> 5;            // 0..3

    const int NCH = (MODE == 0) ? Hh : 2*Hh;
    __shared__ float scw[2*Hh];
    __shared__ float su[Nn*Ff];           // 16 KB
    __shared__ float sred[8];
    __shared__ float sstat[2];
    for (int i = threadIdx.x; i < NCH; i += blockDim.x) scw[i] = cw[hp*NCH + i];
    __syncthreads();

    float w1r[Ff], w2r[Ff];
#pragma unroll
    for (int q = 0; q < Ff; q++) { w1r[q] = f1w[f*Ff + q]; w2r[q] = f2w[f*Ff + q]; }
    float cbv = cb[hp], b1 = f1b[f], b2 = f2b[f];

    float s1 = 0.f, s2 = 0.f;
    for (int n = w; n < Nn; n += 4) {
        float y = cbv;
        if (MODE == 0) {
            const float* ip = g_inc + ((b*Hh)*Nn + n)*Ff + f;
#pragma unroll
            for (int h = 0; h < Hh; h++) y += scw[h] * ip[h*Nn*Ff];
        } else {
            const float* ipa = node   + ((b*Cc)*Nn + n)*Ff + f;
            const float* ipb = g_incm + ((b*Hh)*Nn + n)*Ff + f;
#pragma unroll
            for (int c = 0; c < Cc; c++) y += scw[c] * ipa[c*Nn*Ff];
#pragma unroll
            for (int h = 0; h < Hh; h++) y += scw[Cc + h] * ipb[h*Nn*Ff];
        }
        float a0=0.f,a1=0.f,a2=0.f,a3=0.f;
#pragma unroll
        for (int q = 0; q < Ff; q += 4) {
            a0 += __shfl_sync(0xffffffffu, y, q+0) * w1r[q+0];
            a1 += __shfl_sync(0xffffffffu, y, q+1) * w1r[q+1];
            a2 += __shfl_sync(0xffffffffu, y, q+2) * w1r[q+2];
            a3 += __shfl_sync(0xffffffffu, y, q+3) * w1r[q+3];
        }
        float u1 = silu_f(b1 + ((a0+a1)+(a2+a3)));
        a0=a1=a2=a3=0.f;
#pragma unroll
        for (int q = 0; q < Ff; q += 4) {
            a0 += __shfl_sync(0xffffffffu, u1, q+0) * w2r[q+0];
            a1 += __shfl_sync(0xffffffffu, u1, q+1) * w2r[q+1];
            a2 += __shfl_sync(0xffffffffu, u1, q+2) * w2r[q+2];
            a3 += __shfl_sync(0xffffffffu, u1, q+3) * w2r[q+3];
        }
        float u2 = silu_f(b2 + ((a0+a1)+(a2+a3)));
        su[n*Ff + f] = u2;
        s1 += u2; s2 += u2*u2;
    }
#pragma unroll
    for (int o = 16; o; o >>= 1) {
        s1 += __shfl_down_sync(0xffffffffu, s1, o);
        s2 += __shfl_down_sync(0xffffffffu, s2, o);
    }
    if (f == 0) { sred[w] = s1; sred[4 + w] = s2; }
    __syncthreads();
    if (threadIdx.x == 0) {
        float T1 = sred[0] + sred[1] + sred[2] + sred[3];
        float T2 = sred[4] + sred[5] + sred[6] + sred[7];
        const float invc = 1.f / (float)(Nn * Ff);
        float mu  = T1 * invc;
        float var = T2 * invc - mu*mu;
        sstat[0] = mu;
        sstat[1] = rsqrtf(var + LN_EPS);
    }
    __syncthreads();
    float mu = sstat[0], inv = sstat[1];
    for (int n = w; n < Nn; n += 4) {
        float v = (su[n*Ff + f] - mu) * inv * lg[n*Ff + f] + lb[n*Ff + f];
        int oidx = ((b*Hh + hp)*Nn + n)*Ff + f;
        if (MODE == 0) {
            g_incm[oidx] = v;
        } else {
            out[oidx] = v * nmask[b*Nn + n];
        }
    }
}

// ---------------- launch ----------------
extern "C" void kernel_launch(void* const* d_in, const int* in_sizes, int n_in,
                              void* d_out, int out_size) {
    const float* node   = (const float*)d_in[0];
    const float* nmask  = (const float*)d_in[3];
    const float* emask  = (const float*)d_in[4];
    const float* e_cw   = (const float*)d_in[5];
    const float* e_cb   = (const float*)d_in[6];
    const float* e_f1w  = (const float*)d_in[7];
    const float* e_f1b  = (const float*)d_in[8];
    const float* e_f2w  = (const float*)d_in[9];
    const float* e_f2b  = (const float*)d_in[10];
    const float* e_lng  = (const float*)d_in[11];
    const float* e_lnb  = (const float*)d_in[12];
    const float* att_w  = (const float*)d_in[13];
    const float* att_b  = (const float*)d_in[14];
    const float* n_cw   = (const float*)d_in[15];
    const float* n_cb   = (const float*)d_in[16];
    const float* n_f1w  = (const float*)d_in[17];
    const float* n_f1b  = (const float*)d_in[18];
    const float* n_f2w  = (const float*)d_in[19];
    const float* n_f2b  = (const float*)d_in[20];
    const float* n_lng  = (const float*)d_in[21];
    const float* n_lnb  = (const float*)d_in[22];
    const float* ne_cw  = (const float*)d_in[23];
    const float* ne_cb  = (const float*)d_in[24];
    const float* ne_f1w = (const float*)d_in[25];
    const float* ne_f1b = (const float*)d_in[26];
    const float* ne_f2w = (const float*)d_in[27];
    const float* ne_f2b = (const float*)d_in[28];
    const float* ne_lng = (const float*)d_in[29];
    const float* ne_lnb = (const float*)d_in[30];

    float* out_node = (float*)d_out;                       // (B,H,N,F)
    float* out_mij  = (float*)d_out + Bn*Hh*Nn*Ff;         // (B,H,E,F)

    k1_node_pre<<<Bn*Hh*Nn, 32>>>(node, e_cw, e_cb, e_f1w, e_f1b);
    k2_edgeA   <<<Bn*Hh*Nn, 256>>>(e_f2w, e_f2b);
    k3_stats   <<<Bn*Hh, 128>>>();
    {
        dim3 grid(Ee*Ff/4/256, Bn);                        // 508 x 2
        k4a_att<<<grid, 256>>>(emask, e_lng, e_lnb, att_w, att_b);
    }
    k4b_edgeB  <<<Bn*Hh*Nn, 128>>>(emask, e_lng, e_lnb, out_mij);
    k_node_mlp<0><<<Bn*Hh, 128>>>(nullptr, n_cw, n_cb, n_f1w, n_f1b,
                                  n_f2w, n_f2b, n_lng, n_lnb, nullptr, nullptr);
    k_node_mlp<1><<<Bn*Hh, 128>>>(node, ne_cw, ne_cb, ne_f1w, ne_f1b,
                                  ne_f2w, ne_f2b, ne_lng, ne_lnb, nmask, out_node);
}

// round 12
// speedup vs baseline: 1.2777x; 1.2777x over previous
#include <cuda_runtime.h>
#include <cuda_bf16.h>

#define Bn 2
#define Cc 32
#define Hh 32
#define Nn 128
#define Ff 32
#define Ee 16256          // N*(N-1)
#define NM1 127
#define LN_EPS 1e-5f

// ---------------- scratch (device globals; no allocation) ----------------
__device__ float g_A  [Bn*Hh*Nn*Ff];   // fc1(conv(sender-part))
__device__ float g_Bc [Bn*Hh*Nn*Ff];   // fc1(conv(receiver-part)) + bias terms
__device__ float g_X  [Bn*Hh*Ee*Ff];   // pre-LN edge activations (133 MB)
__device__ float g_part[Bn*Hh*Nn*2];   // per-(b,h,r) partial (sum, sumsq)
__device__ float g_stats[Bn*Hh*2];     // (mu, invstd) per (b,h)
__device__ float g_att [Bn*Ee*Ff];     // attention (4.2 MB)
__device__ float g_inc [Bn*Hh*Nn*Ff];  // incoming (already /N)
__device__ float g_incm[Bn*Hh*Nn*Ff];  // incoming after node MLP

// single-MUFU silu / sigmoid via HW tanh (sm_75+: MUFU.TANH)
__device__ __forceinline__ float silu_f(float x) {
    float t;
    asm("tanh.approx.f32 %0, %1;" : "=f"(t) : "f"(x * 0.5f));
    return fmaf(0.5f * x, t, 0.5f * x);
}
__device__ __forceinline__ float sigm_f(float x) {
    float t;
    asm("tanh.approx.f32 %0, %1;" : "=f"(t) : "f"(x * 0.5f));
    return fmaf(0.5f, t, 0.5f);
}

// ---------------- K1: per-node A / Bc precompute ----------------
__global__ void k1_node_pre(const float* __restrict__ node,
                            const float* __restrict__ ecw,
                            const float* __restrict__ ecb,
                            const float* __restrict__ f1w,
                            const float* __restrict__ f1b) {
    int bid = blockIdx.x;                 // (b,h,n) linear
    int n = bid & (Nn-1);
    int h = (bid >> 7) & (Hh-1);
    int b = bid >> 12;
    int g = threadIdx.x;

    const float* np_ = node + ((b*Cc)*Nn + n)*Ff + g;
    const float* w   = ecw + h*2*Cc;
    float S = 0.f, R = 0.f;
#pragma unroll
    for (int c = 0; c < Cc; c++) {
        float v = np_[c*Nn*Ff];
        S += w[c]      * v;
        R += w[Cc + c] * v;
    }
    float A0=0.f,A1=0.f,A2=0.f,A3=0.f, B0=0.f,B1=0.f,B2=0.f,B3=0.f, rs=0.f;
#pragma unroll
    for (int f = 0; f < Ff; f += 4) {
        float w0 = f1w[g*Ff + f+0], w1 = f1w[g*Ff + f+1];
        float w2_ = f1w[g*Ff + f+2], w3 = f1w[g*Ff + f+3];
        A0 += w0 * __shfl_sync(0xffffffffu, S, f+0);
        A1 += w1 * __shfl_sync(0xffffffffu, S, f+1);
        A2 += w2_ * __shfl_sync(0xffffffffu, S, f+2);
        A3 += w3 * __shfl_sync(0xffffffffu, S, f+3);
        B0 += w0 * __shfl_sync(0xffffffffu, R, f+0);
        B1 += w1 * __shfl_sync(0xffffffffu, R, f+1);
        B2 += w2_ * __shfl_sync(0xffffffffu, R, f+2);
        B3 += w3 * __shfl_sync(0xffffffffu, R, f+3);
        rs += w0 + w1 + w2_ + w3;
    }
    int o = ((b*Hh + h)*Nn + n)*Ff + g;
    g_A [o] = (A0+A1)+(A2+A3);
    g_Bc[o] = (B0+B1)+(B2+B3) + ecb[h]*rs + f1b[g];
}

// ---------------- K2: edge pass A — x = silu(fc2(silu(A[s]+Bc[r]))), stats ----------------
// 256 threads = 8 warps; warp handles j = w, w+8, ... ; lane = feature.
// fc2 matvec via per-warp smem staging + broadcast LDS.128.
__global__ void k2_edgeA(const float* __restrict__ f2w,
                         const float* __restrict__ f2b) {
    int bid = blockIdx.x;                 // (b,h,r)
    int r = bid & (Nn-1);
    int h = (bid >> 7) & (Hh-1);
    int b = bid >> 12;
    int g = threadIdx.x & 31;
    int w = threadIdx.x >> 5;             // 0..7
    int bh = b*Hh + h;

    __shared__ float su[8][2][32];        // per-warp double-buffered u stage

    float bc = g_Bc[(bh*Nn + r)*Ff + g];
    float4 w2r[8];
#pragma unroll
    for (int q = 0; q < 8; q++) w2r[q] = ((const float4*)(f2w + g*Ff))[q];
    float b2 = f2b[g];

    const float* Abase = g_A + (size_t)bh*Nn*Ff + g;
    float s1 = 0.f, s2 = 0.f;
    int ebase = bh*Ee + r*NM1;
    int buf = 0;
    for (int j = w; j < NM1; j += 8) {
        int s = j + (j >= r);
        float u = silu_f(Abase[s*Ff] + bc);
        su[w][buf][g] = u;
        __syncwarp();
        float v0=0.f,v1=0.f,v2=0.f,v3=0.f;
#pragma unroll
        for (int q = 0; q < 8; q++) {
            float4 u4 = *(const float4*)&su[w][buf][q*4];
            v0 += u4.x * w2r[q].x;
            v1 += u4.y * w2r[q].y;
            v2 += u4.z * w2r[q].z;
            v3 += u4.w * w2r[q].w;
        }
        float x = silu_f(b2 + ((v0+v1)+(v2+v3)));
        g_X[(size_t)(ebase + j)*Ff + g] = x;
        s1 += x; s2 += x*x;
        buf ^= 1;
    }
#pragma unroll
    for (int o = 16; o; o >>= 1) {
        s1 += __shfl_down_sync(0xffffffffu, s1, o);
        s2 += __shfl_down_sync(0xffffffffu, s2, o);
    }
    __shared__ float sm[16];
    if (g == 0) { sm[w] = s1; sm[8 + w] = s2; }
    __syncthreads();
    if (threadIdx.x == 0) {
        float t1 = 0.f, t2 = 0.f;
#pragma unroll
        for (int q = 0; q < 8; q++) { t1 += sm[q]; t2 += sm[8+q]; }
        g_part[(bh*Nn + r)*2 + 0] = t1;
        g_part[(bh*Nn + r)*2 + 1] = t2;
    }
}

// ---------------- K3: finalize LN stats per (b,h) ----------------
__global__ void k3_stats() {
    int bh = blockIdx.x;
    int t  = threadIdx.x;                 // 0..127 = r
    float s1 = g_part[(bh*Nn + t)*2 + 0];
    float s2 = g_part[(bh*Nn + t)*2 + 1];
#pragma unroll
    for (int o = 16; o; o >>= 1) {
        s1 += __shfl_down_sync(0xffffffffu, s1, o);
        s2 += __shfl_down_sync(0xffffffffu, s2, o);
    }
    __shared__ float sm[8];
    if ((t & 31) == 0) { sm[t >> 5] = s1; sm[4 + (t >> 5)] = s2; }
    __syncthreads();
    if (t == 0) {
        float T1 = sm[0] + sm[1] + sm[2] + sm[3];
        float T2 = sm[4] + sm[5] + sm[6] + sm[7];
        const float invc = 1.f / (float)(Ee * Ff);
        float mu  = T1 * invc;
        float var = T2 * invc - mu*mu;
        g_stats[bh*2 + 0] = mu;
        g_stats[bh*2 + 1] = rsqrtf(var + LN_EPS);
    }
}

// ---------------- K4a: attention (h-reduction factored out) ----------------
__global__ void k4a_att(const float* __restrict__ emask,
                        const float* __restrict__ lng,
                        const float* __restrict__ lnb,
                        const float* __restrict__ attw,
                        const float* __restrict__ attb) {
    int b  = blockIdx.y;
    int i4 = blockIdx.x * blockDim.x + threadIdx.x;   // float4 index into (E,F)

    __shared__ float swh[Hh];
    __shared__ float sc[2];                            // c1, c0
    if (threadIdx.x < Hh) {
        int h = threadIdx.x;
        swh[h] = attw[h] * g_stats[(b*Hh + h)*2 + 1];
    }
    __syncthreads();
    if (threadIdx.x == 0) {
        float c1 = 0.f, c0 = 0.f;
#pragma unroll
        for (int h = 0; h < Hh; h++) {
            c1 += swh[h] * g_stats[(b*Hh + h)*2 + 0];
            c0 += attw[h];
        }
        sc[0] = c1; sc[1] = c0;
    }
    __syncthreads();

    const float4* xb = (const float4*)(g_X + (size_t)b*Hh*Ee*Ff) + i4;
    float4 T = make_float4(0.f, 0.f, 0.f, 0.f);
#pragma unroll
    for (int h = 0; h < Hh; h++) {
        float wv = swh[h];
        float4 x = xb[(size_t)h * (Ee*Ff/4)];
        T.x += wv*x.x; T.y += wv*x.y; T.z += wv*x.z; T.w += wv*x.w;
    }
    float c1 = sc[0], c0 = sc[1];
    float ab = attb[0];
    int e = i4 >> 3;                                  // 8 float4 per edge row
    float em = emask[b*Ee + e];
    float4 lg = ((const float4*)lng)[i4];
    float4 lb = ((const float4*)lnb)[i4];
    float4 a;
    a.x = sigm_f(em*(lg.x*(T.x - c1) + lb.x*c0) + ab);
    a.y = sigm_f(em*(lg.y*(T.y - c1) + lb.y*c0) + ab);
    a.z = sigm_f(em*(lg.z*(T.z - c1) + lb.z*c0) + ab);
    a.w = sigm_f(em*(lg.w*(T.w - c1) + lb.w*c0) + ab);
    ((float4*)(g_att + (size_t)b*Ee*Ff))[i4] = a;
}

// ---------------- K4b: mij out + segmented incoming — float4, no loop barriers ----------------
__global__ void k4b_edgeB(const float* __restrict__ emask,
                          const float* __restrict__ lng,
                          const float* __restrict__ lnb,
                          float* __restrict__ out_mij) {
    int bid = blockIdx.x;
    int r = bid & (Nn-1);
    int h = (bid >> 7) & (Hh-1);
    int b = bid >> 12;
    int tid = threadIdx.x;
    int f4  = tid & 7;                    // which float4 of the 32-f row
    int bh = b*Hh + h;

    float mu  = g_stats[bh*2 + 0];
    float inv = g_stats[bh*2 + 1];

    const float4* xb  = (const float4*)(g_X    + (size_t)bh*Ee*Ff);
    float4*       mo  = (float4*)      (out_mij + (size_t)bh*Ee*Ff);
    const float4* atp = (const float4*)(g_att  + (size_t)b*Ee*Ff);
    const float4* lgp = (const float4*)lng;
    const float4* lbp = (const float4*)lnb;
    const float*  emb = emask + b*Ee;

    int e0 = r*NM1;
    int jr = tid >> 3;                    // 0..15
    float4 acc = make_float4(0.f, 0.f, 0.f, 0.f);
#pragma unroll 2
    for (int j = jr; j < NM1; j += 16) {
        int e = e0 + j;
        int o = e*8 + f4;
        float  em = emb[e];
        float4 x  = xb[o];
        float4 lg = lgp[o];
        float4 lb = lbp[o];
        float4 at = atp[o];
        float4 m1, mv;
        m1.x = ((x.x - mu)*inv*lg.x + lb.x) * em;
        m1.y = ((x.y - mu)*inv*lg.y + lb.y) * em;
        m1.z = ((x.z - mu)*inv*lg.z + lb.z) * em;
        m1.w = ((x.w - mu)*inv*lg.w + lb.w) * em;
        mv.x = m1.x * em; mv.y = m1.y * em; mv.z = m1.z * em; mv.w = m1.w * em;
        mo[o] = mv;
        acc.x += m1.x * at.x * em;
        acc.y += m1.y * at.y * em;
        acc.z += m1.z * at.z * em;
        acc.w += m1.w * at.w * em;
    }

    __shared__ float sacc[128*4];
    *(float4*)&sacc[tid*4] = acc;
    __syncthreads();
    if (tid < 32) {
        int c = tid >> 2, comp = tid & 3; // f = c*4 + comp == tid
        float t = 0.f;
#pragma unroll
        for (int k = 0; k < 16; k++) t += sacc[(c + 8*k)*4 + comp];
        g_inc[(bh*Nn + r)*Ff + tid] = t * (1.f/(float)Nn);
    }
}

// ---------------- node-side MLP4d: one block per (b,h'), whole LN in-block ----------------
template<int MODE>
__global__ void k_node_mlp(const float* __restrict__ node,
                           const float* __restrict__ cw,
                           const float* __restrict__ cb,
                           const float* __restrict__ f1w,
                           const float* __restrict__ f1b,
                           const float* __restrict__ f2w,
                           const float* __restrict__ f2b,
                           const float* __restrict__ lg,
                           const float* __restrict__ lb,
                           const float* __restrict__ nmask,
                           float* __restrict__ out) {
    int hp = blockIdx.x & (Hh-1);
    int b  = blockIdx.x >> 5;
    int f  = threadIdx.x & 31;
    int w  = threadIdx.x >> 5;            // 0..3

    const int NCH = (MODE == 0) ? Hh : 2*Hh;
    __shared__ float scw[2*Hh];
    __shared__ float su[Nn*Ff];           // 16 KB
    __shared__ float sred[8];
    __shared__ float sstat[2];
    for (int i = threadIdx.x; i < NCH; i += blockDim.x) scw[i] = cw[hp*NCH + i];
    __syncthreads();

    float w1r[Ff], w2r[Ff];
#pragma unroll
    for (int q = 0; q < Ff; q++) { w1r[q] = f1w[f*Ff + q]; w2r[q] = f2w[f*Ff + q]; }
    float cbv = cb[hp], b1 = f1b[f], b2 = f2b[f];

    float s1 = 0.f, s2 = 0.f;
    for (int n = w; n < Nn; n += 4) {
        float y = cbv;
        if (MODE == 0) {
            const float* ip = g_inc + ((b*Hh)*Nn + n)*Ff + f;
#pragma unroll
            for (int h = 0; h < Hh; h++) y += scw[h] * ip[h*Nn*Ff];
        } else {
            const float* ipa = node   + ((b*Cc)*Nn + n)*Ff + f;
            const float* ipb = g_incm + ((b*Hh)*Nn + n)*Ff + f;
#pragma unroll
            for (int c = 0; c < Cc; c++) y += scw[c] * ipa[c*Nn*Ff];
#pragma unroll
            for (int h = 0; h < Hh; h++) y += scw[Cc + h] * ipb[h*Nn*Ff];
        }
        float a0=0.f,a1=0.f,a2=0.f,a3=0.f;
#pragma unroll
        for (int q = 0; q < Ff; q += 4) {
            a0 += __shfl_sync(0xffffffffu, y, q+0) * w1r[q+0];
            a1 += __shfl_sync(0xffffffffu, y, q+1) * w1r[q+1];
            a2 += __shfl_sync(0xffffffffu, y, q+2) * w1r[q+2];
            a3 += __shfl_sync(0xffffffffu, y, q+3) * w1r[q+3];
        }
        float u1 = silu_f(b1 + ((a0+a1)+(a2+a3)));
        a0=a1=a2=a3=0.f;
#pragma unroll
        for (int q = 0; q < Ff; q += 4) {
            a0 += __shfl_sync(0xffffffffu, u1, q+0) * w2r[q+0];
            a1 += __shfl_sync(0xffffffffu, u1, q+1) * w2r[q+1];
            a2 += __shfl_sync(0xffffffffu, u1, q+2) * w2r[q+2];
            a3 += __shfl_sync(0xffffffffu, u1, q+3) * w2r[q+3];
        }
        float u2 = silu_f(b2 + ((a0+a1)+(a2+a3)));
        su[n*Ff + f] = u2;
        s1 += u2; s2 += u2*u2;
    }
#pragma unroll
    for (int o = 16; o; o >>= 1) {
        s1 += __shfl_down_sync(0xffffffffu, s1, o);
        s2 += __shfl_down_sync(0xffffffffu, s2, o);
    }
    if (f == 0) { sred[w] = s1; sred[4 + w] = s2; }
    __syncthreads();
    if (threadIdx.x == 0) {
        float T1 = sred[0] + sred[1] + sred[2] + sred[3];
        float T2 = sred[4] + sred[5] + sred[6] + sred[7];
        const float invc = 1.f / (float)(Nn * Ff);
        float mu  = T1 * invc;
        float var = T2 * invc - mu*mu;
        sstat[0] = mu;
        sstat[1] = rsqrtf(var + LN_EPS);
    }
    __syncthreads();
    float mu = sstat[0], inv = sstat[1];
    for (int n = w; n < Nn; n += 4) {
        float v = (su[n*Ff + f] - mu) * inv * lg[n*Ff + f] + lb[n*Ff + f];
        int oidx = ((b*Hh + hp)*Nn + n)*Ff + f;
        if (MODE == 0) {
            g_incm[oidx] = v;
        } else {
            out[oidx] = v * nmask[b*Nn + n];
        }
    }
}

// ---------------- launch ----------------
extern "C" void kernel_launch(void* const* d_in, const int* in_sizes, int n_in,
                              void* d_out, int out_size) {
    const float* node   = (const float*)d_in[0];
    const float* nmask  = (const float*)d_in[3];
    const float* emask  = (const float*)d_in[4];
    const float* e_cw   = (const float*)d_in[5];
    const float* e_cb   = (const float*)d_in[6];
    const float* e_f1w  = (const float*)d_in[7];
    const float* e_f1b  = (const float*)d_in[8];
    const float* e_f2w  = (const float*)d_in[9];
    const float* e_f2b  = (const float*)d_in[10];
    const float* e_lng  = (const float*)d_in[11];
    const float* e_lnb  = (const float*)d_in[12];
    const float* att_w  = (const float*)d_in[13];
    const float* att_b  = (const float*)d_in[14];
    const float* n_cw   = (const float*)d_in[15];
    const float* n_cb   = (const float*)d_in[16];
    const float* n_f1w  = (const float*)d_in[17];
    const float* n_f1b  = (const float*)d_in[18];
    const float* n_f2w  = (const float*)d_in[19];
    const float* n_f2b  = (const float*)d_in[20];
    const float* n_lng  = (const float*)d_in[21];
    const float* n_lnb  = (const float*)d_in[22];
    const float* ne_cw  = (const float*)d_in[23];
    const float* ne_cb  = (const float*)d_in[24];
    const float* ne_f1w = (const float*)d_in[25];
    const float* ne_f1b = (const float*)d_in[26];
    const float* ne_f2w = (const float*)d_in[27];
    const float* ne_f2b = (const float*)d_in[28];
    const float* ne_lng = (const float*)d_in[29];
    const float* ne_lnb = (const float*)d_in[30];

    float* out_node = (float*)d_out;                       // (B,H,N,F)
    float* out_mij  = (float*)d_out + Bn*Hh*Nn*Ff;         // (B,H,E,F)

    k1_node_pre<<<Bn*Hh*Nn, 32>>>(node, e_cw, e_cb, e_f1w, e_f1b);
    k2_edgeA   <<<Bn*Hh*Nn, 256>>>(e_f2w, e_f2b);
    k3_stats   <<<Bn*Hh, 128>>>();
    {
        dim3 grid(Ee*Ff/4/256, Bn);                        // 508 x 2
        k4a_att<<<grid, 256>>>(emask, e_lng, e_lnb, att_w, att_b);
    }
    k4b_edgeB  <<<Bn*Hh*Nn, 128>>>(emask, e_lng, e_lnb, out_mij);
    k_node_mlp<0><<<Bn*Hh, 128>>>(nullptr, n_cw, n_cb, n_f1w, n_f1b,
                                  n_f2w, n_f2b, n_lng, n_lnb, nullptr, nullptr);
    k_node_mlp<1><<<Bn*Hh, 128>>>(node, ne_cw, ne_cb, ne_f1w, ne_f1b,
                                  ne_f2w, ne_f2b, ne_lng, ne_lnb, nmask, out_node);
}

// round 14
// speedup vs baseline: 1.5010x; 1.1747x over previous
#include <cuda_runtime.h>
#include <cuda_bf16.h>

#define Bn 2
#define Cc 32
#define Hh 32
#define Nn 128
#define Ff 32
#define Ee 16256          // N*(N-1)
#define NM1 127
#define LN_EPS 1e-5f

// ---------------- scratch (device globals; no allocation) ----------------
__device__ float g_A  [Bn*Hh*Nn*Ff];   // fc1(conv(sender-part))
__device__ float g_Bc [Bn*Hh*Nn*Ff];   // fc1(conv(receiver-part)) + bias terms
__device__ float g_X  [Bn*Hh*Ee*Ff];   // pre-LN edge activations (133 MB)
__device__ float g_part[Bn*Hh*Nn*2];   // per-(b,h,r) partial (sum, sumsq)
__device__ float g_stats[Bn*Hh*2];     // (mu, invstd) per (b,h)
__device__ float g_att [Bn*Ee*Ff];     // attention (4.2 MB)
__device__ float g_inc [Bn*Hh*Nn*Ff];  // incoming (already /N)
__device__ float g_incm[Bn*Hh*Nn*Ff];  // incoming after node MLP

__device__ __forceinline__ float silu_f(float x) {
    return x * __frcp_rn(1.f + __expf(-x));
}
__device__ __forceinline__ float sigm_f(float x) {
    return __frcp_rn(1.f + __expf(-x));
}

// ---------------- dummy (ncu capture alignment) ----------------
__global__ void k_dummy() {}

// ---------------- K1: per-node A / Bc precompute ----------------
__global__ void k1_node_pre(const float* __restrict__ node,
                            const float* __restrict__ ecw,
                            const float* __restrict__ ecb,
                            const float* __restrict__ f1w,
                            const float* __restrict__ f1b) {
    int bid = blockIdx.x;                 // (b,h,n) linear
    int n = bid & (Nn-1);
    int h = (bid >> 7) & (Hh-1);
    int b = bid >> 12;
    int g = threadIdx.x;

    const float* np_ = node + ((b*Cc)*Nn + n)*Ff + g;
    const float* w   = ecw + h*2*Cc;
    float S = 0.f, R = 0.f;
#pragma unroll
    for (int c = 0; c < Cc; c++) {
        float v = np_[c*Nn*Ff];
        S += w[c]      * v;
        R += w[Cc + c] * v;
    }
    float A0=0.f,A1=0.f,A2=0.f,A3=0.f, B0=0.f,B1=0.f,B2=0.f,B3=0.f, rs=0.f;
#pragma unroll
    for (int f = 0; f < Ff; f += 4) {
        float w0 = f1w[g*Ff + f+0], w1 = f1w[g*Ff + f+1];
        float w2_ = f1w[g*Ff + f+2], w3 = f1w[g*Ff + f+3];
        A0 += w0 * __shfl_sync(0xffffffffu, S, f+0);
        A1 += w1 * __shfl_sync(0xffffffffu, S, f+1);
        A2 += w2_ * __shfl_sync(0xffffffffu, S, f+2);
        A3 += w3 * __shfl_sync(0xffffffffu, S, f+3);
        B0 += w0 * __shfl_sync(0xffffffffu, R, f+0);
        B1 += w1 * __shfl_sync(0xffffffffu, R, f+1);
        B2 += w2_ * __shfl_sync(0xffffffffu, R, f+2);
        B3 += w3 * __shfl_sync(0xffffffffu, R, f+3);
        rs += w0 + w1 + w2_ + w3;
    }
    int o = ((b*Hh + h)*Nn + n)*Ff + g;
    g_A [o] = (A0+A1)+(A2+A3);
    g_Bc[o] = (B0+B1)+(B2+B3) + ecb[h]*rs + f1b[g];
}

// ---------------- K2: edge pass A — phase-split ----------------
// block = (b,h,r), 256 threads.
// Phase A: u[e][q] = silu(A[s][q]+Bc[r][q]) for all 127 edges, parallel LDG.
// Phase B: warp = 16 edges, lane = f, broadcast LDS.128, 2-edge ILP, no syncs.
__global__ void k2_edgeA(const float* __restrict__ f2w,
                         const float* __restrict__ f2b) {
    int bid = blockIdx.x;                 // (b,h,r)
    int r = bid & (Nn-1);
    int h = (bid >> 7) & (Hh-1);
    int b = bid >> 12;
    int tid = threadIdx.x;
    int bh = b*Hh + h;

    __shared__ __align__(16) float su[NM1*Ff];   // u[e][q], 16.25 KB
    __shared__ float sBc[Ff];
    __shared__ float sm[16];

    if (tid < Ff) sBc[tid] = g_Bc[(bh*Nn + r)*Ff + tid];
    __syncthreads();

    // ---- phase A: parallel u computation (MLP ~16) ----
    const float* Ab = g_A + (size_t)bh*Nn*Ff;
    for (int i = tid; i < NM1*Ff; i += 256) {
        int e = i >> 5, q = i & 31;
        int s = e + (e >= r);
        su[i] = silu_f(Ab[s*Ff + q] + sBc[q]);
    }
    __syncthreads();

    // ---- phase B: x = silu(fc2(u)), warp = 16 edges, no syncs ----
    int f = tid & 31, w = tid >> 5;
    float4 w2r[8];
#pragma unroll
    for (int q = 0; q < 8; q++) w2r[q] = ((const float4*)(f2w + f*Ff))[q];
    float b2 = f2b[f];

    float s1 = 0.f, s2 = 0.f;
    int ebase = bh*Ee + r*NM1;
    int e_lo = w*16;
    int e_hi = e_lo + 16; if (e_hi > NM1) e_hi = NM1;

    int e = e_lo;
    for (; e + 1 < e_hi; e += 2) {
        const float4* ua = (const float4*)&su[e*Ff];
        const float4* ub = (const float4*)&su[(e+1)*Ff];
        float a0=0.f,a1=0.f,a2=0.f,a3=0.f;
        float c0=0.f,c1=0.f,c2=0.f,c3=0.f;
#pragma unroll
        for (int q = 0; q < 8; q++) {
            float4 va = ua[q], vb = ub[q], wq = w2r[q];
            a0 += va.x*wq.x; a1 += va.y*wq.y; a2 += va.z*wq.z; a3 += va.w*wq.w;
            c0 += vb.x*wq.x; c1 += vb.y*wq.y; c2 += vb.z*wq.z; c3 += vb.w*wq.w;
        }
        float xa = silu_f(b2 + ((a0+a1)+(a2+a3)));
        float xb = silu_f(b2 + ((c0+c1)+(c2+c3)));
        g_X[(size_t)(ebase + e  )*Ff + f] = xa;
        g_X[(size_t)(ebase + e+1)*Ff + f] = xb;
        s1 += xa + xb; s2 += xa*xa + xb*xb;
    }
    if (e < e_hi) {
        const float4* ua = (const float4*)&su[e*Ff];
        float a0=0.f,a1=0.f,a2=0.f,a3=0.f;
#pragma unroll
        for (int q = 0; q < 8; q++) {
            float4 va = ua[q], wq = w2r[q];
            a0 += va.x*wq.x; a1 += va.y*wq.y; a2 += va.z*wq.z; a3 += va.w*wq.w;
        }
        float xa = silu_f(b2 + ((a0+a1)+(a2+a3)));
        g_X[(size_t)(ebase + e)*Ff + f] = xa;
        s1 += xa; s2 += xa*xa;
    }

    // ---- stats reduce ----
#pragma unroll
    for (int o = 16; o; o >>= 1) {
        s1 += __shfl_down_sync(0xffffffffu, s1, o);
        s2 += __shfl_down_sync(0xffffffffu, s2, o);
    }
    if (f == 0) { sm[w] = s1; sm[8 + w] = s2; }
    __syncthreads();
    if (tid == 0) {
        float t1 = 0.f, t2 = 0.f;
#pragma unroll
        for (int q = 0; q < 8; q++) { t1 += sm[q]; t2 += sm[8+q]; }
        g_part[(bh*Nn + r)*2 + 0] = t1;
        g_part[(bh*Nn + r)*2 + 1] = t2;
    }
}

// ---------------- K3: finalize LN stats per (b,h) ----------------
__global__ void k3_stats() {
    int bh = blockIdx.x;
    int t  = threadIdx.x;                 // 0..127 = r
    float s1 = g_part[(bh*Nn + t)*2 + 0];
    float s2 = g_part[(bh*Nn + t)*2 + 1];
#pragma unroll
    for (int o = 16; o; o >>= 1) {
        s1 += __shfl_down_sync(0xffffffffu, s1, o);
        s2 += __shfl_down_sync(0xffffffffu, s2, o);
    }
    __shared__ float sm[8];
    if ((t & 31) == 0) { sm[t >> 5] = s1; sm[4 + (t >> 5)] = s2; }
    __syncthreads();
    if (t == 0) {
        float T1 = sm[0] + sm[1] + sm[2] + sm[3];
        float T2 = sm[4] + sm[5] + sm[6] + sm[7];
        const float invc = 1.f / (float)(Ee * Ff);
        float mu  = T1 * invc;
        float var = T2 * invc - mu*mu;
        g_stats[bh*2 + 0] = mu;
        g_stats[bh*2 + 1] = rsqrtf(var + LN_EPS);
    }
}

// ---------------- K4a: attention (h-reduction factored out) ----------------
__global__ void k4a_att(const float* __restrict__ emask,
                        const float* __restrict__ lng,
                        const float* __restrict__ lnb,
                        const float* __restrict__ attw,
                        const float* __restrict__ attb) {
    int b  = blockIdx.y;
    int i4 = blockIdx.x * blockDim.x + threadIdx.x;   // float4 index into (E,F)

    __shared__ float swh[Hh];
    __shared__ float sc[2];                            // c1, c0
    if (threadIdx.x < Hh) {
        int h = threadIdx.x;
        swh[h] = attw[h] * g_stats[(b*Hh + h)*2 + 1];
    }
    __syncthreads();
    if (threadIdx.x == 0) {
        float c1 = 0.f, c0 = 0.f;
#pragma unroll
        for (int h = 0; h < Hh; h++) {
            c1 += swh[h] * g_stats[(b*Hh + h)*2 + 0];
            c0 += attw[h];
        }
        sc[0] = c1; sc[1] = c0;
    }
    __syncthreads();

    const float4* xb = (const float4*)(g_X + (size_t)b*Hh*Ee*Ff) + i4;
    float4 T = make_float4(0.f, 0.f, 0.f, 0.f);
#pragma unroll
    for (int h = 0; h < Hh; h++) {
        float wv = swh[h];
        float4 x = xb[(size_t)h * (Ee*Ff/4)];
        T.x += wv*x.x; T.y += wv*x.y; T.z += wv*x.z; T.w += wv*x.w;
    }
    float c1 = sc[0], c0 = sc[1];
    float ab = attb[0];
    int e = i4 >> 3;                                  // 8 float4 per edge row
    float em = emask[b*Ee + e];
    float4 lg = ((const float4*)lng)[i4];
    float4 lb = ((const float4*)lnb)[i4];
    float4 a;
    a.x = sigm_f(em*(lg.x*(T.x - c1) + lb.x*c0) + ab);
    a.y = sigm_f(em*(lg.y*(T.y - c1) + lb.y*c0) + ab);
    a.z = sigm_f(em*(lg.z*(T.z - c1) + lb.z*c0) + ab);
    a.w = sigm_f(em*(lg.w*(T.w - c1) + lb.w*c0) + ab);
    ((float4*)(g_att + (size_t)b*Ee*Ff))[i4] = a;
}

// ---------------- K4b: mij out + segmented incoming — float4, no loop barriers ----------------
__global__ void k4b_edgeB(const float* __restrict__ emask,
                          const float* __restrict__ lng,
                          const float* __restrict__ lnb,
                          float* __restrict__ out_mij) {
    int bid = blockIdx.x;
    int r = bid & (Nn-1);
    int h = (bid >> 7) & (Hh-1);
    int b = bid >> 12;
    int tid = threadIdx.x;
    int f4  = tid & 7;                    // which float4 of the 32-f row
    int bh = b*Hh + h;

    float mu  = g_stats[bh*2 + 0];
    float inv = g_stats[bh*2 + 1];

    const float4* xb  = (const float4*)(g_X    + (size_t)bh*Ee*Ff);
    float4*       mo  = (float4*)      (out_mij + (size_t)bh*Ee*Ff);
    const float4* atp = (const float4*)(g_att  + (size_t)b*Ee*Ff);
    const float4* lgp = (const float4*)lng;
    const float4* lbp = (const float4*)lnb;
    const float*  emb = emask + b*Ee;

    int e0 = r*NM1;
    int jr = tid >> 3;                    // 0..15
    float4 acc = make_float4(0.f, 0.f, 0.f, 0.f);
#pragma unroll 2
    for (int j = jr; j < NM1; j += 16) {
        int e = e0 + j;
        int o = e*8 + f4;
        float  em = emb[e];
        float4 x  = xb[o];
        float4 lg = lgp[o];
        float4 lb = lbp[o];
        float4 at = atp[o];
        float4 m1, mv;
        m1.x = ((x.x - mu)*inv*lg.x + lb.x) * em;
        m1.y = ((x.y - mu)*inv*lg.y + lb.y) * em;
        m1.z = ((x.z - mu)*inv*lg.z + lb.z) * em;
        m1.w = ((x.w - mu)*inv*lg.w + lb.w) * em;
        mv.x = m1.x * em; mv.y = m1.y * em; mv.z = m1.z * em; mv.w = m1.w * em;
        mo[o] = mv;
        acc.x += m1.x * at.x * em;
        acc.y += m1.y * at.y * em;
        acc.z += m1.z * at.z * em;
        acc.w += m1.w * at.w * em;
    }

    __shared__ float sacc[128*4];
    *(float4*)&sacc[tid*4] = acc;
    __syncthreads();
    if (tid < 32) {
        int c = tid >> 2, comp = tid & 3; // f = c*4 + comp == tid
        float t = 0.f;
#pragma unroll
        for (int k = 0; k < 16; k++) t += sacc[(c + 8*k)*4 + comp];
        g_inc[(bh*Nn + r)*Ff + tid] = t * (1.f/(float)Nn);
    }
}

// ---------------- node-side MLP4d: one block per (b,h'), whole LN in-block ----------------
template<int MODE>
__global__ void k_node_mlp(const float* __restrict__ node,
                           const float* __restrict__ cw,
                           const float* __restrict__ cb,
                           const float* __restrict__ f1w,
                           const float* __restrict__ f1b,
                           const float* __restrict__ f2w,
                           const float* __restrict__ f2b,
                           const float* __restrict__ lg,
                           const float* __restrict__ lb,
                           const float* __restrict__ nmask,
                           float* __restrict__ out) {
    int hp = blockIdx.x & (Hh-1);
    int b  = blockIdx.x >> 5;
    int f  = threadIdx.x & 31;
    int w  = threadIdx.x >> 5;            // 0..3

    const int NCH = (MODE == 0) ? Hh : 2*Hh;
    __shared__ float scw[2*Hh];
    __shared__ float su[Nn*Ff];           // 16 KB
    __shared__ float sred[8];
    __shared__ float sstat[2];
    for (int i = threadIdx.x; i < NCH; i += blockDim.x) scw[i] = cw[hp*NCH + i];
    __syncthreads();

    float w1r[Ff], w2r[Ff];
#pragma unroll
    for (int q = 0; q < Ff; q++) { w1r[q] = f1w[f*Ff + q]; w2r[q] = f2w[f*Ff + q]; }
    float cbv = cb[hp], b1 = f1b[f], b2 = f2b[f];

    float s1 = 0.f, s2 = 0.f;
    for (int n = w; n < Nn; n += 4) {
        float y = cbv;
        if (MODE == 0) {
            const float* ip = g_inc + ((b*Hh)*Nn + n)*Ff + f;
#pragma unroll
            for (int h = 0; h < Hh; h++) y += scw[h] * ip[h*Nn*Ff];
        } else {
            const float* ipa = node   + ((b*Cc)*Nn + n)*Ff + f;
            const float* ipb = g_incm + ((b*Hh)*Nn + n)*Ff + f;
#pragma unroll
            for (int c = 0; c < Cc; c++) y += scw[c] * ipa[c*Nn*Ff];
#pragma unroll
            for (int h = 0; h < Hh; h++) y += scw[Cc + h] * ipb[h*Nn*Ff];
        }
        float a0=0.f,a1=0.f,a2=0.f,a3=0.f;
#pragma unroll
        for (int q = 0; q < Ff; q += 4) {
            a0 += __shfl_sync(0xffffffffu, y, q+0) * w1r[q+0];
            a1 += __shfl_sync(0xffffffffu, y, q+1) * w1r[q+1];
            a2 += __shfl_sync(0xffffffffu, y, q+2) * w1r[q+2];
            a3 += __shfl_sync(0xffffffffu, y, q+3) * w1r[q+3];
        }
        float u1 = silu_f(b1 + ((a0+a1)+(a2+a3)));
        a0=a1=a2=a3=0.f;
#pragma unroll
        for (int q = 0; q < Ff; q += 4) {
            a0 += __shfl_sync(0xffffffffu, u1, q+0) * w2r[q+0];
            a1 += __shfl_sync(0xffffffffu, u1, q+1) * w2r[q+1];
            a2 += __shfl_sync(0xffffffffu, u1, q+2) * w2r[q+2];
            a3 += __shfl_sync(0xffffffffu, u1, q+3) * w2r[q+3];
        }
        float u2 = silu_f(b2 + ((a0+a1)+(a2+a3)));
        su[n*Ff + f] = u2;
        s1 += u2; s2 += u2*u2;
    }
#pragma unroll
    for (int o = 16; o; o >>= 1) {
        s1 += __shfl_down_sync(0xffffffffu, s1, o);
        s2 += __shfl_down_sync(0xffffffffu, s2, o);
    }
    if (f == 0) { sred[w] = s1; sred[4 + w] = s2; }
    __syncthreads();
    if (threadIdx.x == 0) {
        float T1 = sred[0] + sred[1] + sred[2] + sred[3];
        float T2 = sred[4] + sred[5] + sred[6] + sred[7];
        const float invc = 1.f / (float)(Nn * Ff);
        float mu  = T1 * invc;
        float var = T2 * invc - mu*mu;
        sstat[0] = mu;
        sstat[1] = rsqrtf(var + LN_EPS);
    }
    __syncthreads();
    float mu = sstat[0], inv = sstat[1];
    for (int n = w; n < Nn; n += 4) {
        float v = (su[n*Ff + f] - mu) * inv * lg[n*Ff + f] + lb[n*Ff + f];
        int oidx = ((b*Hh + hp)*Nn + n)*Ff + f;
        if (MODE == 0) {
            g_incm[oidx] = v;
        } else {
            out[oidx] = v * nmask[b*Nn + n];
        }
    }
}

// ---------------- launch ----------------
extern "C" void kernel_launch(void* const* d_in, const int* in_sizes, int n_in,
                              void* d_out, int out_size) {
    const float* node   = (const float*)d_in[0];
    const float* nmask  = (const float*)d_in[3];
    const float* emask  = (const float*)d_in[4];
    const float* e_cw   = (const float*)d_in[5];
    const float* e_cb   = (const float*)d_in[6];
    const float* e_f1w  = (const float*)d_in[7];
    const float* e_f1b  = (const float*)d_in[8];
    const float* e_f2w  = (const float*)d_in[9];
    const float* e_f2b  = (const float*)d_in[10];
    const float* e_lng  = (const float*)d_in[11];
    const float* e_lnb  = (const float*)d_in[12];
    const float* att_w  = (const float*)d_in[13];
    const float* att_b  = (const float*)d_in[14];
    const float* n_cw   = (const float*)d_in[15];
    const float* n_cb   = (const float*)d_in[16];
    const float* n_f1w  = (const float*)d_in[17];
    const float* n_f1b  = (const float*)d_in[18];
    const float* n_f2w  = (const float*)d_in[19];
    const float* n_f2b  = (const float*)d_in[20];
    const float* n_lng  = (const float*)d_in[21];
    const float* n_lnb  = (const float*)d_in[22];
    const float* ne_cw  = (const float*)d_in[23];
    const float* ne_cb  = (const float*)d_in[24];
    const float* ne_f1w = (const float*)d_in[25];
    const float* ne_f1b = (const float*)d_in[26];
    const float* ne_f2w = (const float*)d_in[27];
    const float* ne_f2b = (const float*)d_in[28];
    const float* ne_lng = (const float*)d_in[29];
    const float* ne_lnb = (const float*)d_in[30];

    float* out_node = (float*)d_out;                       // (B,H,N,F)
    float* out_mij  = (float*)d_out + Bn*Hh*Nn*Ff;         // (B,H,E,F)

    k1_node_pre<<<Bn*Hh*Nn, 32>>>(node, e_cw, e_cb, e_f1w, e_f1b);
    k_dummy<<<1, 32>>>();   // ncu capture alignment: put k2 at cycle idx 3
    k_dummy<<<1, 32>>>();
    k2_edgeA   <<<Bn*Hh*Nn, 256>>>(e_f2w, e_f2b);
    k3_stats   <<<Bn*Hh, 128>>>();
    {
        dim3 grid(Ee*Ff/4/256, Bn);                        // 508 x 2
        k4a_att<<<grid, 256>>>(emask, e_lng, e_lnb, att_w, att_b);
    }
    k4b_edgeB  <<<Bn*Hh*Nn, 128>>>(emask, e_lng, e_lnb, out_mij);
    k_node_mlp<0><<<Bn*Hh, 128>>>(nullptr, n_cw, n_cb, n_f1w, n_f1b,
                                  n_f2w, n_f2b, n_lng, n_lnb, nullptr, nullptr);
    k_node_mlp<1><<<Bn*Hh, 128>>>(node, ne_cw, ne_cb, ne_f1w, ne_f1b,
                                  ne_f2w, ne_f2b, ne_lng, ne_lnb, nmask, out_node);
}

// round 15
// speedup vs baseline: 1.7223x; 1.1475x over previous
#include <cuda_runtime.h>
#include <cuda_bf16.h>

#define Bn 2
#define Cc 32
#define Hh 32
#define Nn 128
#define Ff 32
#define Ee 16256          // N*(N-1)
#define NM1 127
#define LN_EPS 1e-5f

// ---------------- scratch (device globals; no allocation) ----------------
__device__ float g_A  [Bn*Hh*Nn*Ff];   // fc1(conv(sender-part))
__device__ float g_Bc [Bn*Hh*Nn*Ff];   // fc1(conv(receiver-part)) + bias terms
__device__ float g_X  [Bn*Hh*Ee*Ff];   // pre-LN edge activations (133 MB)
__device__ float g_part[Bn*Hh*Nn*2];   // per-(b,h,r) partial (sum, sumsq)
__device__ float g_stats[Bn*Hh*2];     // (mu, invstd) per (b,h)
__device__ float g_att [Bn*Ee*Ff];     // attention (4.2 MB)
__device__ float g_inc [Bn*Hh*Nn*Ff];  // incoming (already /N)
__device__ float g_incm[Bn*Hh*Nn*Ff];  // incoming after node MLP

__device__ __forceinline__ float silu_f(float x) {
    return x * __frcp_rn(1.f + __expf(-x));
}
__device__ __forceinline__ float sigm_f(float x) {
    return __frcp_rn(1.f + __expf(-x));
}

// ---------------- dummy (ncu capture alignment) ----------------
__global__ void k_dummy() {}

// ---------------- K1: per-node A / Bc precompute ----------------
__global__ void k1_node_pre(const float* __restrict__ node,
                            const float* __restrict__ ecw,
                            const float* __restrict__ ecb,
                            const float* __restrict__ f1w,
                            const float* __restrict__ f1b) {
    int bid = blockIdx.x;                 // (b,h,n) linear
    int n = bid & (Nn-1);
    int h = (bid >> 7) & (Hh-1);
    int b = bid >> 12;
    int g = threadIdx.x;

    const float* np_ = node + ((b*Cc)*Nn + n)*Ff + g;
    const float* w   = ecw + h*2*Cc;
    float S = 0.f, R = 0.f;
#pragma unroll
    for (int c = 0; c < Cc; c++) {
        float v = np_[c*Nn*Ff];
        S += w[c]      * v;
        R += w[Cc + c] * v;
    }
    float A0=0.f,A1=0.f,A2=0.f,A3=0.f, B0=0.f,B1=0.f,B2=0.f,B3=0.f, rs=0.f;
#pragma unroll
    for (int f = 0; f < Ff; f += 4) {
        float w0 = f1w[g*Ff + f+0], w1 = f1w[g*Ff + f+1];
        float w2_ = f1w[g*Ff + f+2], w3 = f1w[g*Ff + f+3];
        A0 += w0 * __shfl_sync(0xffffffffu, S, f+0);
        A1 += w1 * __shfl_sync(0xffffffffu, S, f+1);
        A2 += w2_ * __shfl_sync(0xffffffffu, S, f+2);
        A3 += w3 * __shfl_sync(0xffffffffu, S, f+3);
        B0 += w0 * __shfl_sync(0xffffffffu, R, f+0);
        B1 += w1 * __shfl_sync(0xffffffffu, R, f+1);
        B2 += w2_ * __shfl_sync(0xffffffffu, R, f+2);
        B3 += w3 * __shfl_sync(0xffffffffu, R, f+3);
        rs += w0 + w1 + w2_ + w3;
    }
    int o = ((b*Hh + h)*Nn + n)*Ff + g;
    g_A [o] = (A0+A1)+(A2+A3);
    g_Bc[o] = (B0+B1)+(B2+B3) + ecb[h]*rs + f1b[g];
}

// ---------------- K2: edge pass A — phase-split + register-tiled fc2 GEMM ----------------
// block = (b,h,r), 256 threads.
// Phase A: uT[q][e] = silu(A[s][q]+Bc[r][q]), transposed, e=127 padded 0.
// Phase B: warp = 16 edges; lane = (le 0..3, lf 0..7); thread tile 4e x 4f;
//          per q: 1 LDS.128 (u) + 1 LDS.128 (w2T) + 16 FMA. No syncs.
__global__ void k2_edgeA(const float* __restrict__ f2w,
                         const float* __restrict__ f2b) {
    int bid = blockIdx.x;                 // (b,h,r)
    int r = bid & (Nn-1);
    int h = (bid >> 7) & (Hh-1);
    int b = bid >> 12;
    int tid = threadIdx.x;
    int bh = b*Hh + h;

    __shared__ __align__(16) float uT[32*132];   // q rows (stride 132), e cols; 16.9 KB
    __shared__ __align__(16) float w2T[32*32];   // w2T[q][f] = f2w[f][q]; 4 KB
    __shared__ float sBc[Ff];
    __shared__ float sm[16];

    if (tid < Ff) sBc[tid] = g_Bc[(bh*Nn + r)*Ff + tid];
    for (int i = tid; i < Ff*Ff; i += 256) {     // transpose f2w into smem
        int f = i >> 5, q = i & 31;
        w2T[q*Ff + f] = f2w[i];
    }
    __syncthreads();

    // ---- phase A: u computation (coalesced LDG, transposed STS) ----
    const float* Ab = g_A + (size_t)bh*Nn*Ff;
    for (int i = tid; i < NM1*Ff; i += 256) {
        int e = i >> 5, q = i & 31;
        int s = e + (e >= r);
        uT[q*132 + e] = silu_f(Ab[s*Ff + q] + sBc[q]);
    }
    if (tid < 32) uT[tid*132 + 127] = 0.f;       // pad edge 127
    __syncthreads();

    // ---- phase B: register-tiled GEMM ----
    int lane = tid & 31, w = tid >> 5;
    int le = lane >> 3, lf = lane & 7;
    int e0 = w*16 + le*4;                 // 4 edges e0..e0+3 (e0 max 124)
    int f0 = lf*4;

    float acc[4][4];
#pragma unroll
    for (int i = 0; i < 4; i++)
#pragma unroll
        for (int j = 0; j < 4; j++) acc[i][j] = 0.f;

    const float* uTb = uT + e0;
    const float* wTb = w2T + f0;
#pragma unroll 8
    for (int q = 0; q < 32; q++) {
        float4 uu = *(const float4*)(uTb + q*132);
        float4 wv = *(const float4*)(wTb + q*Ff);
        acc[0][0] += uu.x*wv.x; acc[0][1] += uu.x*wv.y; acc[0][2] += uu.x*wv.z; acc[0][3] += uu.x*wv.w;
        acc[1][0] += uu.y*wv.x; acc[1][1] += uu.y*wv.y; acc[1][2] += uu.y*wv.z; acc[1][3] += uu.y*wv.w;
        acc[2][0] += uu.z*wv.x; acc[2][1] += uu.z*wv.y; acc[2][2] += uu.z*wv.z; acc[2][3] += uu.z*wv.w;
        acc[3][0] += uu.w*wv.x; acc[3][1] += uu.w*wv.y; acc[3][2] += uu.w*wv.z; acc[3][3] += uu.w*wv.w;
    }

    float b20 = f2b[f0+0], b21 = f2b[f0+1], b22 = f2b[f0+2], b23 = f2b[f0+3];
    float s1 = 0.f, s2 = 0.f;
    size_t ebase = (size_t)bh*Ee + (size_t)r*NM1;
#pragma unroll
    for (int i = 0; i < 4; i++) {
        int e = e0 + i;
        if (e < NM1) {
            float4 x;
            x.x = silu_f(acc[i][0] + b20);
            x.y = silu_f(acc[i][1] + b21);
            x.z = silu_f(acc[i][2] + b22);
            x.w = silu_f(acc[i][3] + b23);
            *(float4*)&g_X[(ebase + e)*Ff + f0] = x;
            s1 += (x.x + x.y) + (x.z + x.w);
            s2 += (x.x*x.x + x.y*x.y) + (x.z*x.z + x.w*x.w);
        }
    }

    // ---- stats reduce ----
#pragma unroll
    for (int o = 16; o; o >>= 1) {
        s1 += __shfl_down_sync(0xffffffffu, s1, o);
        s2 += __shfl_down_sync(0xffffffffu, s2, o);
    }
    if (lane == 0) { sm[w] = s1; sm[8 + w] = s2; }
    __syncthreads();
    if (tid == 0) {
        float t1 = 0.f, t2 = 0.f;
#pragma unroll
        for (int q = 0; q < 8; q++) { t1 += sm[q]; t2 += sm[8+q]; }
        g_part[(bh*Nn + r)*2 + 0] = t1;
        g_part[(bh*Nn + r)*2 + 1] = t2;
    }
}

// ---------------- K3: finalize LN stats per (b,h) ----------------
__global__ void k3_stats() {
    int bh = blockIdx.x;
    int t  = threadIdx.x;                 // 0..127 = r
    float s1 = g_part[(bh*Nn + t)*2 + 0];
    float s2 = g_part[(bh*Nn + t)*2 + 1];
#pragma unroll
    for (int o = 16; o; o >>= 1) {
        s1 += __shfl_down_sync(0xffffffffu, s1, o);
        s2 += __shfl_down_sync(0xffffffffu, s2, o);
    }
    __shared__ float sm[8];
    if ((t & 31) == 0) { sm[t >> 5] = s1; sm[4 + (t >> 5)] = s2; }
    __syncthreads();
    if (t == 0) {
        float T1 = sm[0] + sm[1] + sm[2] + sm[3];
        float T2 = sm[4] + sm[5] + sm[6] + sm[7];
        const float invc = 1.f / (float)(Ee * Ff);
        float mu  = T1 * invc;
        float var = T2 * invc - mu*mu;
        g_stats[bh*2 + 0] = mu;
        g_stats[bh*2 + 1] = rsqrtf(var + LN_EPS);
    }
}

// ---------------- K4a: attention (h-reduction factored out) ----------------
__global__ void k4a_att(const float* __restrict__ emask,
                        const float* __restrict__ lng,
                        const float* __restrict__ lnb,
                        const float* __restrict__ attw,
                        const float* __restrict__ attb) {
    int b  = blockIdx.y;
    int i4 = blockIdx.x * blockDim.x + threadIdx.x;   // float4 index into (E,F)

    __shared__ float swh[Hh];
    __shared__ float sc[2];                            // c1, c0
    if (threadIdx.x < Hh) {
        int h = threadIdx.x;
        swh[h] = attw[h] * g_stats[(b*Hh + h)*2 + 1];
    }
    __syncthreads();
    if (threadIdx.x == 0) {
        float c1 = 0.f, c0 = 0.f;
#pragma unroll
        for (int h = 0; h < Hh; h++) {
            c1 += swh[h] * g_stats[(b*Hh + h)*2 + 0];
            c0 += attw[h];
        }
        sc[0] = c1; sc[1] = c0;
    }
    __syncthreads();

    const float4* xb = (const float4*)(g_X + (size_t)b*Hh*Ee*Ff) + i4;
    float4 T = make_float4(0.f, 0.f, 0.f, 0.f);
#pragma unroll
    for (int h = 0; h < Hh; h++) {
        float wv = swh[h];
        float4 x = xb[(size_t)h * (Ee*Ff/4)];
        T.x += wv*x.x; T.y += wv*x.y; T.z += wv*x.z; T.w += wv*x.w;
    }
    float c1 = sc[0], c0 = sc[1];
    float ab = attb[0];
    int e = i4 >> 3;                                  // 8 float4 per edge row
    float em = emask[b*Ee + e];
    float4 lg = ((const float4*)lng)[i4];
    float4 lb = ((const float4*)lnb)[i4];
    float4 a;
    a.x = sigm_f(em*(lg.x*(T.x - c1) + lb.x*c0) + ab);
    a.y = sigm_f(em*(lg.y*(T.y - c1) + lb.y*c0) + ab);
    a.z = sigm_f(em*(lg.z*(T.z - c1) + lb.z*c0) + ab);
    a.w = sigm_f(em*(lg.w*(T.w - c1) + lb.w*c0) + ab);
    ((float4*)(g_att + (size_t)b*Ee*Ff))[i4] = a;
}

// ---------------- K4b: mij out + segmented incoming — float4, no loop barriers ----------------
__global__ void k4b_edgeB(const float* __restrict__ emask,
                          const float* __restrict__ lng,
                          const float* __restrict__ lnb,
                          float* __restrict__ out_mij) {
    int bid = blockIdx.x;
    int r = bid & (Nn-1);
    int h = (bid >> 7) & (Hh-1);
    int b = bid >> 12;
    int tid = threadIdx.x;
    int f4  = tid & 7;                    // which float4 of the 32-f row
    int bh = b*Hh + h;

    float mu  = g_stats[bh*2 + 0];
    float inv = g_stats[bh*2 + 1];

    const float4* xb  = (const float4*)(g_X    + (size_t)bh*Ee*Ff);
    float4*       mo  = (float4*)      (out_mij + (size_t)bh*Ee*Ff);
    const float4* atp = (const float4*)(g_att  + (size_t)b*Ee*Ff);
    const float4* lgp = (const float4*)lng;
    const float4* lbp = (const float4*)lnb;
    const float*  emb = emask + b*Ee;

    int e0 = r*NM1;
    int jr = tid >> 3;                    // 0..15
    float4 acc = make_float4(0.f, 0.f, 0.f, 0.f);
#pragma unroll 2
    for (int j = jr; j < NM1; j += 16) {
        int e = e0 + j;
        int o = e*8 + f4;
        float  em = emb[e];
        float4 x  = xb[o];
        float4 lg = lgp[o];
        float4 lb = lbp[o];
        float4 at = atp[o];
        float4 m1, mv;
        m1.x = ((x.x - mu)*inv*lg.x + lb.x) * em;
        m1.y = ((x.y - mu)*inv*lg.y + lb.y) * em;
        m1.z = ((x.z - mu)*inv*lg.z + lb.z) * em;
        m1.w = ((x.w - mu)*inv*lg.w + lb.w) * em;
        mv.x = m1.x * em; mv.y = m1.y * em; mv.z = m1.z * em; mv.w = m1.w * em;
        mo[o] = mv;
        acc.x += m1.x * at.x * em;
        acc.y += m1.y * at.y * em;
        acc.z += m1.z * at.z * em;
        acc.w += m1.w * at.w * em;
    }

    __shared__ float sacc[128*4];
    *(float4*)&sacc[tid*4] = acc;
    __syncthreads();
    if (tid < 32) {
        int c = tid >> 2, comp = tid & 3; // f = c*4 + comp == tid
        float t = 0.f;
#pragma unroll
        for (int k = 0; k < 16; k++) t += sacc[(c + 8*k)*4 + comp];
        g_inc[(bh*Nn + r)*Ff + tid] = t * (1.f/(float)Nn);
    }
}

// ---------------- node-side MLP4d: one block per (b,h'), whole LN in-block ----------------
template<int MODE>
__global__ void k_node_mlp(const float* __restrict__ node,
                           const float* __restrict__ cw,
                           const float* __restrict__ cb,
                           const float* __restrict__ f1w,
                           const float* __restrict__ f1b,
                           const float* __restrict__ f2w,
                           const float* __restrict__ f2b,
                           const float* __restrict__ lg,
                           const float* __restrict__ lb,
                           const float* __restrict__ nmask,
                           float* __restrict__ out) {
    int hp = blockIdx.x & (Hh-1);
    int b  = blockIdx.x >> 5;
    int f  = threadIdx.x & 31;
    int w  = threadIdx.x >> 5;            // 0..3

    const int NCH = (MODE == 0) ? Hh : 2*Hh;
    __shared__ float scw[2*Hh];
    __shared__ float su[Nn*Ff];           // 16 KB
    __shared__ float sred[8];
    __shared__ float sstat[2];
    for (int i = threadIdx.x; i < NCH; i += blockDim.x) scw[i] = cw[hp*NCH + i];
    __syncthreads();

    float w1r[Ff], w2r[Ff];
#pragma unroll
    for (int q = 0; q < Ff; q++) { w1r[q] = f1w[f*Ff + q]; w2r[q] = f2w[f*Ff + q]; }
    float cbv = cb[hp], b1 = f1b[f], b2 = f2b[f];

    float s1 = 0.f, s2 = 0.f;
    for (int n = w; n < Nn; n += 4) {
        float y = cbv;
        if (MODE == 0) {
            const float* ip = g_inc + ((b*Hh)*Nn + n)*Ff + f;
#pragma unroll
            for (int h = 0; h < Hh; h++) y += scw[h] * ip[h*Nn*Ff];
        } else {
            const float* ipa = node   + ((b*Cc)*Nn + n)*Ff + f;
            const float* ipb = g_incm + ((b*Hh)*Nn + n)*Ff + f;
#pragma unroll
            for (int c = 0; c < Cc; c++) y += scw[c] * ipa[c*Nn*Ff];
#pragma unroll
            for (int h = 0; h < Hh; h++) y += scw[Cc + h] * ipb[h*Nn*Ff];
        }
        float a0=0.f,a1=0.f,a2=0.f,a3=0.f;
#pragma unroll
        for (int q = 0; q < Ff; q += 4) {
            a0 += __shfl_sync(0xffffffffu, y, q+0) * w1r[q+0];
            a1 += __shfl_sync(0xffffffffu, y, q+1) * w1r[q+1];
            a2 += __shfl_sync(0xffffffffu, y, q+2) * w1r[q+2];
            a3 += __shfl_sync(0xffffffffu, y, q+3) * w1r[q+3];
        }
        float u1 = silu_f(b1 + ((a0+a1)+(a2+a3)));
        a0=a1=a2=a3=0.f;
#pragma unroll
        for (int q = 0; q < Ff; q += 4) {
            a0 += __shfl_sync(0xffffffffu, u1, q+0) * w2r[q+0];
            a1 += __shfl_sync(0xffffffffu, u1, q+1) * w2r[q+1];
            a2 += __shfl_sync(0xffffffffu, u1, q+2) * w2r[q+2];
            a3 += __shfl_sync(0xffffffffu, u1, q+3) * w2r[q+3];
        }
        float u2 = silu_f(b2 + ((a0+a1)+(a2+a3)));
        su[n*Ff + f] = u2;
        s1 += u2; s2 += u2*u2;
    }
#pragma unroll
    for (int o = 16; o; o >>= 1) {
        s1 += __shfl_down_sync(0xffffffffu, s1, o);
        s2 += __shfl_down_sync(0xffffffffu, s2, o);
    }
    if (f == 0) { sred[w] = s1; sred[4 + w] = s2; }
    __syncthreads();
    if (threadIdx.x == 0) {
        float T1 = sred[0] + sred[1] + sred[2] + sred[3];
        float T2 = sred[4] + sred[5] + sred[6] + sred[7];
        const float invc = 1.f / (float)(Nn * Ff);
        float mu  = T1 * invc;
        float var = T2 * invc - mu*mu;
        sstat[0] = mu;
        sstat[1] = rsqrtf(var + LN_EPS);
    }
    __syncthreads();
    float mu = sstat[0], inv = sstat[1];
    for (int n = w; n < Nn; n += 4) {
        float v = (su[n*Ff + f] - mu) * inv * lg[n*Ff + f] + lb[n*Ff + f];
        int oidx = ((b*Hh + hp)*Nn + n)*Ff + f;
        if (MODE == 0) {
            g_incm[oidx] = v;
        } else {
            out[oidx] = v * nmask[b*Nn + n];
        }
    }
}

// ---------------- launch ----------------
extern "C" void kernel_launch(void* const* d_in, const int* in_sizes, int n_in,
                              void* d_out, int out_size) {
    const float* node   = (const float*)d_in[0];
    const float* nmask  = (const float*)d_in[3];
    const float* emask  = (const float*)d_in[4];
    const float* e_cw   = (const float*)d_in[5];
    const float* e_cb   = (const float*)d_in[6];
    const float* e_f1w  = (const float*)d_in[7];
    const float* e_f1b  = (const float*)d_in[8];
    const float* e_f2w  = (const float*)d_in[9];
    const float* e_f2b  = (const float*)d_in[10];
    const float* e_lng  = (const float*)d_in[11];
    const float* e_lnb  = (const float*)d_in[12];
    const float* att_w  = (const float*)d_in[13];
    const float* att_b  = (const float*)d_in[14];
    const float* n_cw   = (const float*)d_in[15];
    const float* n_cb   = (const float*)d_in[16];
    const float* n_f1w  = (const float*)d_in[17];
    const float* n_f1b  = (const float*)d_in[18];
    const float* n_f2w  = (const float*)d_in[19];
    const float* n_f2b  = (const float*)d_in[20];
    const float* n_lng  = (const float*)d_in[21];
    const float* n_lnb  = (const float*)d_in[22];
    const float* ne_cw  = (const float*)d_in[23];
    const float* ne_cb  = (const float*)d_in[24];
    const float* ne_f1w = (const float*)d_in[25];
    const float* ne_f1b = (const float*)d_in[26];
    const float* ne_f2w = (const float*)d_in[27];
    const float* ne_f2b = (const float*)d_in[28];
    const float* ne_lng = (const float*)d_in[29];
    const float* ne_lnb = (const float*)d_in[30];

    float* out_node = (float*)d_out;                       // (B,H,N,F)
    float* out_mij  = (float*)d_out + Bn*Hh*Nn*Ff;         // (B,H,E,F)

    k1_node_pre<<<Bn*Hh*Nn, 32>>>(node, e_cw, e_cb, e_f1w, e_f1b);
    k_dummy<<<1, 32>>>();   // ncu capture alignment: keep k2 at profiled index
    k_dummy<<<1, 32>>>();
    k2_edgeA   <<<Bn*Hh*Nn, 256>>>(e_f2w, e_f2b);
    k3_stats   <<<Bn*Hh, 128>>>();
    {
        dim3 grid(Ee*Ff/4/256, Bn);                        // 508 x 2
        k4a_att<<<grid, 256>>>(emask, e_lng, e_lnb, att_w, att_b);
    }
    k4b_edgeB  <<<Bn*Hh*Nn, 128>>>(emask, e_lng, e_lnb, out_mij);
    k_node_mlp<0><<<Bn*Hh, 128>>>(nullptr, n_cw, n_cb, n_f1w, n_f1b,
                                  n_f2w, n_f2b, n_lng, n_lnb, nullptr, nullptr);
    k_node_mlp<1><<<Bn*Hh, 128>>>(node, ne_cw, ne_cb, ne_f1w, ne_f1b,
                                  ne_f2w, ne_f2b, ne_lng, ne_lnb, nmask, out_node);
}